// round 9
// baseline (speedup 1.0000x reference)
#include <cuda_runtime.h>
#include <cuda_bf16.h>

constexpr int kB = 4, kS = 2048, kD = 1024, kH = 16, kDK = 64;
constexpr int kKS = 3072;  // split K dimension [hi | lo | hi]
constexpr int kCap = 32;   // shortlist capacity per row

__device__ __forceinline__ unsigned smem_u32(const void* p) {
  unsigned a;
  asm("{ .reg .u64 t; cvta.to.shared.u64 t, %1; cvt.u32.u64 %0, t; }"
      : "=r"(a) : "l"(p));
  return a;
}

// ---------------- mma.sync helpers (sm_80-class PTX) ----------------
__device__ __forceinline__ void cpasync16(unsigned dst, const void* src) {
  asm volatile("cp.async.ca.shared.global [%0], [%1], 16;" :: "r"(dst), "l"(src));
}
__device__ __forceinline__ void ldmx4(unsigned* r, unsigned addr) {
  asm volatile("ldmatrix.sync.aligned.m8n8.x4.shared.b16 {%0,%1,%2,%3}, [%4];"
               : "=r"(r[0]), "=r"(r[1]), "=r"(r[2]), "=r"(r[3]) : "r"(addr));
}
__device__ __forceinline__ void mma_bf16(float* d, const unsigned* a,
                                         unsigned b0, unsigned b1) {
  asm volatile(
      "mma.sync.aligned.m16n8k16.row.col.f32.bf16.bf16.f32 "
      "{%0,%1,%2,%3}, {%4,%5,%6,%7}, {%8,%9}, {%0,%1,%2,%3};"
      : "+f"(d[0]), "+f"(d[1]), "+f"(d[2]), "+f"(d[3])
      : "r"(a[0]), "r"(a[1]), "r"(a[2]), "r"(a[3]), "r"(b0), "r"(b1));
}

// ---------------- scratch ----------------
__device__ __align__(16) float g_q [(size_t)kB * kH * kS * kDK];
__device__ __align__(16) float g_k [(size_t)kB * kH * kS * kDK];
__device__ __align__(16) float g_v [(size_t)kB * kH * kS * kDK];
__device__ __align__(16) float g_ao[(size_t)kB * kS * kH * kDK];
__device__ __align__(16) __nv_bfloat16 g_xs [(size_t)kB * kS * kKS];
__device__ __align__(16) __nv_bfloat16 g_ws [(size_t)3 * kH * kDK * kKS];
__device__ __align__(16) __nv_bfloat16 g_wos[(size_t)kD * kKS];
__device__ __align__(16) __nv_bfloat16 g_aos[(size_t)kB * kS * kKS];
__device__ int            g_cnt [(size_t)kB * kH * kS];
__device__ unsigned short g_slot[(size_t)kB * kH * kS * kCap];

__device__ __forceinline__ void split1(float x, unsigned short& h,
                                       unsigned short& l) {
  __nv_bfloat16 hb = __float2bfloat16_rn(x);
  __nv_bfloat16 lb = __float2bfloat16_rn(x - __bfloat162float(hb));
  h = __bfloat16_as_ushort(hb);
  l = __bfloat16_as_ushort(lb);
}

__device__ __forceinline__ void split8(const float* v, uint4& hi, uint4& lo) {
  unsigned short h[8], l[8];
#pragma unroll
  for (int j = 0; j < 8; ++j) split1(v[j], h[j], l[j]);
  hi = make_uint4((unsigned)h[0] | ((unsigned)h[1] << 16),
                  (unsigned)h[2] | ((unsigned)h[3] << 16),
                  (unsigned)h[4] | ((unsigned)h[5] << 16),
                  (unsigned)h[6] | ((unsigned)h[7] << 16));
  lo = make_uint4((unsigned)l[0] | ((unsigned)l[1] << 16),
                  (unsigned)l[2] | ((unsigned)l[3] << 16),
                  (unsigned)l[4] | ((unsigned)l[5] << 16),
                  (unsigned)l[6] | ((unsigned)l[7] << 16));
}

__device__ __forceinline__ uint4 pack8hi(const float* v) {
  unsigned short h[8];
#pragma unroll
  for (int j = 0; j < 8; ++j)
    h[j] = __bfloat16_as_ushort(__float2bfloat16_rn(v[j]));
  return make_uint4((unsigned)h[0] | ((unsigned)h[1] << 16),
                    (unsigned)h[2] | ((unsigned)h[3] << 16),
                    (unsigned)h[4] | ((unsigned)h[5] << 16),
                    (unsigned)h[6] | ((unsigned)h[7] << 16));
}

// ---------------- split kernels ----------------
__global__ __launch_bounds__(256) void split_act_kernel(
    const float* __restrict__ src, __nv_bfloat16* __restrict__ dst) {
  const int m = blockIdx.x;
  const int t = threadIdx.x;
  float4 v = *(const float4*)&src[(size_t)m * kD + t * 4];
  unsigned short h[4], l[4];
  split1(v.x, h[0], l[0]); split1(v.y, h[1], l[1]);
  split1(v.z, h[2], l[2]); split1(v.w, h[3], l[3]);
  uint2 hp = make_uint2((unsigned)h[0] | ((unsigned)h[1] << 16),
                        (unsigned)h[2] | ((unsigned)h[3] << 16));
  uint2 lp = make_uint2((unsigned)l[0] | ((unsigned)l[1] << 16),
                        (unsigned)l[2] | ((unsigned)l[3] << 16));
  __nv_bfloat16* base = dst + (size_t)m * kKS;
  *(uint2*)(base + t * 4) = hp;
  *(uint2*)(base + 1024 + t * 4) = lp;
  *(uint2*)(base + 2048 + t * 4) = hp;
}

__global__ __launch_bounds__(256) void split_w_kernel(
    const float* __restrict__ Wq, const float* __restrict__ Wk,
    const float* __restrict__ Wv) {
  const int ng = blockIdx.x;
  const int mat = ng >> 10;
  const int h = (ng >> 6) & 15;
  const int n = ng & 63;
  const float* W = (mat == 0 ? Wq : (mat == 1 ? Wk : Wv));
  const float* src = W + (size_t)h * kD * kDK + n;
  __nv_bfloat16* dst = g_ws + (size_t)ng * kKS;
#pragma unroll
  for (int it = 0; it < 4; ++it) {
    int d = threadIdx.x + it * 256;
    unsigned short hh, ll;
    split1(src[(size_t)d * kDK], hh, ll);
    dst[d] = __ushort_as_bfloat16(hh);
    dst[1024 + d] = __ushort_as_bfloat16(hh);
    dst[2048 + d] = __ushort_as_bfloat16(ll);
  }
}

__global__ __launch_bounds__(256) void split_wo_kernel(
    const float* __restrict__ Wo) {
  const int n = blockIdx.x;
  __nv_bfloat16* dst = g_wos + (size_t)n * kKS;
#pragma unroll
  for (int it = 0; it < 4; ++it) {
    int d = threadIdx.x + it * 256;
    unsigned short hh, ll;
    split1(Wo[(size_t)d * kD + n], hh, ll);
    dst[d] = __ushort_as_bfloat16(hh);
    dst[1024 + d] = __ushort_as_bfloat16(hh);
    dst[2048 + d] = __ushort_as_bfloat16(ll);
  }
}

// ---------------------------------------------------------------------------
// HMMA GEMM: C[128 x 256] = A[128 x 3072] * B[256 x 3072]^T (bf16 -> f32).
// 256 thr = 8 warps (2M x 4N), warp tile 64x64, B via ldmatrix.x4.
// smem: A 2x16KB + B 2x32KB = 98304 B. 1 block/SM (acc = 128 regs).
// ---------------------------------------------------------------------------
__global__ __launch_bounds__(256, 1) void mm_bf16_kernel(
    const __nv_bfloat16* __restrict__ A, const __nv_bfloat16* __restrict__ Bm,
    float* __restrict__ outP, int mode) {
  extern __shared__ char smem[];
  const unsigned sbase = smem_u32(smem);
  const unsigned aA[2] = {sbase, sbase + 16384};
  const unsigned aB[2] = {sbase + 32768, sbase + 65536};

  const int tid = threadIdx.x;
  const int wid = tid >> 5, lane = tid & 31;
  const int m0 = blockIdx.x * 128, n0 = blockIdx.y * 256;
  const int wm = (wid >> 2) * 64, wn = (wid & 3) * 64;
  const __nv_bfloat16* Asrc = A + (size_t)m0 * kKS;
  const __nv_bfloat16* Bsrc = Bm + (size_t)n0 * kKS;

  float acc[4][8][4];
#pragma unroll
  for (int mi = 0; mi < 4; ++mi)
#pragma unroll
    for (int nj = 0; nj < 8; ++nj)
#pragma unroll
      for (int r = 0; r < 4; ++r) acc[mi][nj][r] = 0.f;

#define STAGE(sbuf, ch)                                                        \
  do {                                                                         \
    _Pragma("unroll") for (int i_ = 0; i_ < 12; ++i_) {                        \
      int idx_ = tid + i_ * 256;                                               \
      if (idx_ < 1024) {                                                       \
        int r_ = idx_ >> 3, sg_ = idx_ & 7;                                    \
        unsigned sw_ = ((unsigned)(sg_ ^ (r_ & 7))) << 4;                      \
        cpasync16(aA[sbuf] + r_ * 128 + sw_,                                   \
                  Asrc + (size_t)r_ * kKS + (ch) * 64 + sg_ * 8);              \
      } else {                                                                 \
        int j_ = idx_ - 1024;                                                  \
        int r_ = j_ >> 3, sg_ = j_ & 7;                                        \
        unsigned sw_ = ((unsigned)(sg_ ^ (r_ & 7))) << 4;                      \
        cpasync16(aB[sbuf] + r_ * 128 + sw_,                                   \
                  Bsrc + (size_t)r_ * kKS + (ch) * 64 + sg_ * 8);              \
      }                                                                        \
    }                                                                          \
    asm volatile("cp.async.commit_group;" ::: "memory");                       \
  } while (0)

  STAGE(0, 0);
  for (int ch = 0; ch < kKS / 64; ++ch) {
    const int s = ch & 1;
    if (ch < kKS / 64 - 1) {
      STAGE(s ^ 1, ch + 1);
      asm volatile("cp.async.wait_group 1;" ::: "memory");
    } else {
      asm volatile("cp.async.wait_group 0;" ::: "memory");
    }
    __syncthreads();
#pragma unroll
    for (int ks = 0; ks < 4; ++ks) {
      unsigned af[4][4], b4[4][4];
      const int cs = ks * 2 + (lane >> 4);
#pragma unroll
      for (int mi = 0; mi < 4; ++mi) {
        int row = wm + mi * 16 + (lane & 15);
        ldmx4(af[mi], aA[s] + row * 128 + ((unsigned)(cs ^ (row & 7)) << 4));
      }
#pragma unroll
      for (int ni = 0; ni < 4; ++ni) {
        int row = wn + ni * 16 + (lane & 15);
        ldmx4(b4[ni], aB[s] + row * 128 + ((unsigned)(cs ^ (row & 7)) << 4));
      }
#pragma unroll
      for (int mi = 0; mi < 4; ++mi)
#pragma unroll
        for (int ni = 0; ni < 4; ++ni) {
          mma_bf16(acc[mi][ni * 2], af[mi], b4[ni][0], b4[ni][2]);
          mma_bf16(acc[mi][ni * 2 + 1], af[mi], b4[ni][1], b4[ni][3]);
        }
    }
    __syncthreads();
  }
#undef STAGE

  const int b = m0 >> 11;
#pragma unroll
  for (int mi = 0; mi < 4; ++mi) {
    int rl = wm + mi * 16 + (lane >> 2);
#pragma unroll
    for (int nj = 0; nj < 8; ++nj) {
      int n = n0 + wn + nj * 8 + (lane & 3) * 2;
      if (mode == 0) {
        int mat = n >> 10, h = (n >> 6) & 15, dk = n & 63;
        float* qkvout = (mat == 0 ? g_q : (mat == 1 ? g_k : g_v));
        size_t rowbase = (size_t)(b * kH + h) * kS + (m0 & (kS - 1));
        *(float2*)&qkvout[(rowbase + rl) * kDK + dk] =
            make_float2(acc[mi][nj][0], acc[mi][nj][1]);
        *(float2*)&qkvout[(rowbase + rl + 8) * kDK + dk] =
            make_float2(acc[mi][nj][2], acc[mi][nj][3]);
      } else {
        int m = m0 + rl;
        *(float2*)&outP[(size_t)m * kD + n] =
            make_float2(acc[mi][nj][0], acc[mi][nj][1]);
        *(float2*)&outP[(size_t)(m + 8) * kD + n] =
            make_float2(acc[mi][nj][2], acc[mi][nj][3]);
      }
    }
  }
}

// ---------------------------------------------------------------------------
// attn_smax: S ~= (Qhi+Qlo) Khi^T via HMMA, online row max + shortlist.
// Score noise from dropping Q*Klo ~ sigma 2; margin 60 keeps inclusion exact
// down to contributions ~e^-36 (invisible at fp32).
// smem: Qhi 16K + Qlo 16K + Khi 16K + cnt 512 + slots 8K = 57856 B.
// ---------------------------------------------------------------------------
__global__ __launch_bounds__(256) void attn_smax_kernel() {
  extern __shared__ char sm[];
  const unsigned sb = smem_u32(sm);
  const unsigned aQhi = sb, aQlo = sb + 16384, aKhi = sb + 32768;
  int* scnt = (int*)(sm + 49152);
  unsigned short* stid = (unsigned short*)(sm + 49664);

  const int tid = threadIdx.x;
  const int warp = tid >> 5, lane = tid & 31;
  const int qt = blockIdx.x, h = blockIdx.y, b = blockIdx.z;
  const int bh = b * kH + h;

  if (tid < 128) scnt[tid] = 0;

  const float* qsrc = g_q + ((size_t)bh * kS + qt * 128) * kDK;
#pragma unroll
  for (int it = 0; it < 4; ++it) {
    int idx = tid + it * 256;
    int row = idx >> 3, g = idx & 7;
    float v[8];
    float4 v0 = *(const float4*)&qsrc[(size_t)row * kDK + g * 8];
    float4 v1 = *(const float4*)&qsrc[(size_t)row * kDK + g * 8 + 4];
    v[0] = v0.x * 0.125f; v[1] = v0.y * 0.125f; v[2] = v0.z * 0.125f;
    v[3] = v0.w * 0.125f; v[4] = v1.x * 0.125f; v[5] = v1.y * 0.125f;
    v[6] = v1.z * 0.125f; v[7] = v1.w * 0.125f;
    uint4 hi, lo;
    split8(v, hi, lo);
    unsigned sw = ((unsigned)(g ^ (row & 7))) << 4;
    *(uint4*)(sm + row * 128 + sw) = hi;
    *(uint4*)(sm + 16384 + row * 128 + sw) = lo;
  }

  float m0 = -3.0e38f, m1 = -3.0e38f;
  const int r0 = (warp << 4) + (lane >> 2);

  for (int kt = 0; kt < kS / 128; ++kt) {
    const float* ksrc = g_k + ((size_t)bh * kS + kt * 128) * kDK;
#pragma unroll
    for (int it = 0; it < 4; ++it) {
      int idx = tid + it * 256;
      int row = idx >> 3, g = idx & 7;
      float v[8];
      float4 v0 = *(const float4*)&ksrc[(size_t)row * kDK + g * 8];
      float4 v1 = *(const float4*)&ksrc[(size_t)row * kDK + g * 8 + 4];
      v[0] = v0.x; v[1] = v0.y; v[2] = v0.z; v[3] = v0.w;
      v[4] = v1.x; v[5] = v1.y; v[6] = v1.z; v[7] = v1.w;
      unsigned sw = ((unsigned)(g ^ (row & 7))) << 4;
      *(uint4*)(sm + 32768 + row * 128 + sw) = pack8hi(v);
    }
    __syncthreads();

    float acc[16][4];
#pragma unroll
    for (int tt = 0; tt < 16; ++tt)
#pragma unroll
      for (int j = 0; j < 4; ++j) acc[tt][j] = 0.f;

#pragma unroll
    for (int kc = 0; kc < 4; ++kc) {
      unsigned aHi[4], aLo[4];
      const int cs = kc * 2 + (lane >> 4);
      int rowq = (warp << 4) + (lane & 15);
      unsigned swq = ((unsigned)(cs ^ (rowq & 7))) << 4;
      ldmx4(aHi, aQhi + rowq * 128 + swq);
      ldmx4(aLo, aQlo + rowq * 128 + swq);
#pragma unroll
      for (int t3 = 0; t3 < 8; ++t3) {
        int rowb = t3 * 16 + (lane & 15);
        unsigned swb = ((unsigned)(cs ^ (rowb & 7))) << 4;
        unsigned kb[4];
        ldmx4(kb, aKhi + rowb * 128 + swb);
        mma_bf16(acc[t3 * 2], aHi, kb[0], kb[2]);
        mma_bf16(acc[t3 * 2], aLo, kb[0], kb[2]);
        mma_bf16(acc[t3 * 2 + 1], aHi, kb[1], kb[3]);
        mma_bf16(acc[t3 * 2 + 1], aLo, kb[1], kb[3]);
      }
    }

    float lm0 = -3.0e38f, lm1 = -3.0e38f;
#pragma unroll
    for (int tt = 0; tt < 16; ++tt) {
      lm0 = fmaxf(lm0, fmaxf(acc[tt][0], acc[tt][1]));
      lm1 = fmaxf(lm1, fmaxf(acc[tt][2], acc[tt][3]));
    }
    lm0 = fmaxf(lm0, __shfl_xor_sync(0xffffffffu, lm0, 1));
    lm0 = fmaxf(lm0, __shfl_xor_sync(0xffffffffu, lm0, 2));
    lm1 = fmaxf(lm1, __shfl_xor_sync(0xffffffffu, lm1, 1));
    lm1 = fmaxf(lm1, __shfl_xor_sync(0xffffffffu, lm1, 2));
    m0 = fmaxf(m0, lm0);
    m1 = fmaxf(m1, lm1);

    float th0 = m0 - 60.f, th1 = m1 - 60.f;
#pragma unroll
    for (int tt = 0; tt < 16; ++tt) {
      int tb = kt * 128 + tt * 8 + (lane & 3) * 2;
      if (acc[tt][0] > th0) {
        int i = atomicAdd(&scnt[r0], 1);
        if (i < kCap) stid[r0 * kCap + i] = (unsigned short)tb;
      }
      if (acc[tt][1] > th0) {
        int i = atomicAdd(&scnt[r0], 1);
        if (i < kCap) stid[r0 * kCap + i] = (unsigned short)(tb + 1);
      }
      if (acc[tt][2] > th1) {
        int i = atomicAdd(&scnt[r0 + 8], 1);
        if (i < kCap) stid[(r0 + 8) * kCap + i] = (unsigned short)tb;
      }
      if (acc[tt][3] > th1) {
        int i = atomicAdd(&scnt[r0 + 8], 1);
        if (i < kCap) stid[(r0 + 8) * kCap + i] = (unsigned short)(tb + 1);
      }
    }
    __syncthreads();
  }

  if (tid < 128) {
    size_t row_g = ((size_t)bh * 16 + qt) * 128 + tid;
    int c = scnt[tid];
    g_cnt[row_g] = c;
    int cc = c < kCap ? c : kCap;
    for (int i = 0; i < cc; ++i) g_slot[row_g * kCap + i] = stid[tid * kCap + i];
  }
}

// ---------------------------------------------------------------------------
// attn_gather: warp per q-row; exact fp32 softmax over shortlist; gather V.
// ---------------------------------------------------------------------------
__global__ __launch_bounds__(256) void attn_gather_kernel() {
  const int warp = threadIdx.x >> 5, lane = threadIdx.x & 31;
  const size_t row_g = (size_t)blockIdx.x * 8 + warp;
  const int qrow = (int)(row_g & 127);
  const int qt = (int)((row_g >> 7) & 15);
  const int h = (int)((row_g >> 11) & 15);
  const int b = (int)(row_g >> 15);
  const int bh = b * kH + h;
  const int sq = qt * 128 + qrow;

  const float* qp = g_q + ((size_t)bh * kS + sq) * kDK;
  const float* kb = g_k + (size_t)bh * kS * kDK;
  const float* vb = g_v + (size_t)bh * kS * kDK;
  float* outp = g_ao + ((size_t)b * kS + sq) * kD + h * kDK;

  const float q0 = qp[lane] * 0.125f, q1 = qp[lane + 32] * 0.125f;
  const int cnt = g_cnt[row_g];

  float m = -3.0e38f, l = 0.f, a0 = 0.f, a1 = 0.f;
  if (cnt <= kCap) {
    const unsigned short* sl = g_slot + row_g * kCap;
    for (int i = 0; i < cnt; ++i) {
      int t = sl[i];
      float d = q0 * kb[(size_t)t * kDK + lane] + q1 * kb[(size_t)t * kDK + lane + 32];
#pragma unroll
      for (int o = 16; o > 0; o >>= 1) d += __shfl_xor_sync(0xffffffffu, d, o);
      m = fmaxf(m, d);
    }
    for (int i = 0; i < cnt; ++i) {
      int t = sl[i];
      float d = q0 * kb[(size_t)t * kDK + lane] + q1 * kb[(size_t)t * kDK + lane + 32];
#pragma unroll
      for (int o = 16; o > 0; o >>= 1) d += __shfl_xor_sync(0xffffffffu, d, o);
      float p = __expf(d - m);
      l += p;
      a0 += p * vb[(size_t)t * kDK + lane];
      a1 += p * vb[(size_t)t * kDK + lane + 32];
    }
  } else {
    for (int t = 0; t < kS; ++t) {
      float d = q0 * kb[(size_t)t * kDK + lane] + q1 * kb[(size_t)t * kDK + lane + 32];
#pragma unroll
      for (int o = 16; o > 0; o >>= 1) d += __shfl_xor_sync(0xffffffffu, d, o);
      float v0 = vb[(size_t)t * kDK + lane], v1 = vb[(size_t)t * kDK + lane + 32];
      if (d > m) {
        float c = __expf(m - d);
        m = d;
        l = l * c + 1.f;
        a0 = a0 * c + v0;
        a1 = a1 * c + v1;
      } else {
        float p = __expf(d - m);
        l += p;
        a0 += p * v0;
        a1 += p * v1;
      }
    }
  }
  float inv = 1.f / l;
  outp[lane] = a0 * inv;
  outp[lane + 32] = a1 * inv;
}

// ---------------------------------------------------------------------------
extern "C" void kernel_launch(void* const* d_in, const int* in_sizes, int n_in,
                              void* d_out, int out_size) {
  (void)in_sizes; (void)n_in; (void)out_size;
  const float* x  = (const float*)d_in[0];
  const float* Wq = (const float*)d_in[1];
  const float* Wk = (const float*)d_in[2];
  const float* Wv = (const float*)d_in[3];
  const float* Wo = (const float*)d_in[4];
  float* out = (float*)d_out;

  static int attr_set = 0;
  if (!attr_set) {
    cudaFuncSetAttribute(mm_bf16_kernel,
                         cudaFuncAttributeMaxDynamicSharedMemorySize, 98304);
    cudaFuncSetAttribute(attn_smax_kernel,
                         cudaFuncAttributeMaxDynamicSharedMemorySize, 57856);
    attr_set = 1;
  }

  __nv_bfloat16* xs;  cudaGetSymbolAddress((void**)&xs, g_xs);
  __nv_bfloat16* ws;  cudaGetSymbolAddress((void**)&ws, g_ws);
  __nv_bfloat16* wos; cudaGetSymbolAddress((void**)&wos, g_wos);
  __nv_bfloat16* aos; cudaGetSymbolAddress((void**)&aos, g_aos);
  float* aop;         cudaGetSymbolAddress((void**)&aop, g_ao);

  split_act_kernel<<<kB * kS, 256>>>(x, xs);
  split_w_kernel<<<3 * kH * kDK, 256>>>(Wq, Wk, Wv);
  split_wo_kernel<<<kD, 256>>>(Wo);
  mm_bf16_kernel<<<dim3(kB * kS / 128, kKS / 256), 256, 98304>>>(xs, ws, nullptr, 0);
  attn_smax_kernel<<<dim3(kS / 128, kH, kB), 256, 57856>>>();
  attn_gather_kernel<<<kB * kH * kS / 8, 256>>>();
  split_act_kernel<<<kB * kS, 256>>>(aop, aos);
  mm_bf16_kernel<<<dim3(kB * kS / 128, kD / 256), 256, 98304>>>(aos, wos, out, 1);
}

// round 10
// speedup vs baseline: 1.1525x; 1.1525x over previous
#include <cuda_runtime.h>
#include <cuda_bf16.h>

constexpr int kB = 4, kS = 2048, kD = 1024, kH = 16, kDK = 64;
constexpr int kKS = 3072;  // split K dimension [hi | lo | hi]
constexpr int kCap = 32;   // shortlist capacity per row

__device__ __forceinline__ unsigned smem_u32(const void* p) {
  unsigned a;
  asm("{ .reg .u64 t; cvta.to.shared.u64 t, %1; cvt.u32.u64 %0, t; }"
      : "=r"(a) : "l"(p));
  return a;
}

// ---------------- mma.sync helpers (sm_80-class PTX) ----------------
__device__ __forceinline__ void cpasync16(unsigned dst, const void* src) {
  asm volatile("cp.async.ca.shared.global [%0], [%1], 16;" :: "r"(dst), "l"(src));
}
__device__ __forceinline__ void ldmx4(unsigned* r, unsigned addr) {
  asm volatile("ldmatrix.sync.aligned.m8n8.x4.shared.b16 {%0,%1,%2,%3}, [%4];"
               : "=r"(r[0]), "=r"(r[1]), "=r"(r[2]), "=r"(r[3]) : "r"(addr));
}
__device__ __forceinline__ void ldmx2(unsigned* r, unsigned addr) {
  asm volatile("ldmatrix.sync.aligned.m8n8.x2.shared.b16 {%0,%1}, [%2];"
               : "=r"(r[0]), "=r"(r[1]) : "r"(addr));
}
__device__ __forceinline__ void mma_bf16(float* d, const unsigned* a,
                                         unsigned b0, unsigned b1) {
  asm volatile(
      "mma.sync.aligned.m16n8k16.row.col.f32.bf16.bf16.f32 "
      "{%0,%1,%2,%3}, {%4,%5,%6,%7}, {%8,%9}, {%0,%1,%2,%3};"
      : "+f"(d[0]), "+f"(d[1]), "+f"(d[2]), "+f"(d[3])
      : "r"(a[0]), "r"(a[1]), "r"(a[2]), "r"(a[3]), "r"(b0), "r"(b1));
}

// ---------------- scratch ----------------
__device__ __align__(16) float g_q [(size_t)kB * kH * kS * kDK];
__device__ __align__(16) float g_k [(size_t)kB * kH * kS * kDK];
__device__ __align__(16) float g_v [(size_t)kB * kH * kS * kDK];
__device__ __align__(16) float g_ao[(size_t)kB * kS * kH * kDK];
__device__ __align__(16) __nv_bfloat16 g_xs [(size_t)kB * kS * kKS];
__device__ __align__(16) __nv_bfloat16 g_ws [(size_t)3 * kH * kDK * kKS];
__device__ __align__(16) __nv_bfloat16 g_wos[(size_t)kD * kKS];
__device__ __align__(16) __nv_bfloat16 g_aos[(size_t)kB * kS * kKS];
__device__ int            g_cnt [(size_t)kB * kH * kS];
__device__ unsigned short g_slot[(size_t)kB * kH * kS * kCap];

__device__ __forceinline__ void split1(float x, unsigned short& h,
                                       unsigned short& l) {
  __nv_bfloat16 hb = __float2bfloat16_rn(x);
  __nv_bfloat16 lb = __float2bfloat16_rn(x - __bfloat162float(hb));
  h = __bfloat16_as_ushort(hb);
  l = __bfloat16_as_ushort(lb);
}

__device__ __forceinline__ uint4 pack8hi(const float* v) {
  unsigned short h[8];
#pragma unroll
  for (int j = 0; j < 8; ++j)
    h[j] = __bfloat16_as_ushort(__float2bfloat16_rn(v[j]));
  return make_uint4((unsigned)h[0] | ((unsigned)h[1] << 16),
                    (unsigned)h[2] | ((unsigned)h[3] << 16),
                    (unsigned)h[4] | ((unsigned)h[5] << 16),
                    (unsigned)h[6] | ((unsigned)h[7] << 16));
}

// ---------------- split kernels ----------------
__global__ __launch_bounds__(256) void split_act_kernel(
    const float* __restrict__ src, __nv_bfloat16* __restrict__ dst) {
  const int m = blockIdx.x;
  const int t = threadIdx.x;
  float4 v = *(const float4*)&src[(size_t)m * kD + t * 4];
  unsigned short h[4], l[4];
  split1(v.x, h[0], l[0]); split1(v.y, h[1], l[1]);
  split1(v.z, h[2], l[2]); split1(v.w, h[3], l[3]);
  uint2 hp = make_uint2((unsigned)h[0] | ((unsigned)h[1] << 16),
                        (unsigned)h[2] | ((unsigned)h[3] << 16));
  uint2 lp = make_uint2((unsigned)l[0] | ((unsigned)l[1] << 16),
                        (unsigned)l[2] | ((unsigned)l[3] << 16));
  __nv_bfloat16* base = dst + (size_t)m * kKS;
  *(uint2*)(base + t * 4) = hp;
  *(uint2*)(base + 1024 + t * 4) = lp;
  *(uint2*)(base + 2048 + t * 4) = hp;
}

__global__ __launch_bounds__(256) void split_w_kernel(
    const float* __restrict__ Wq, const float* __restrict__ Wk,
    const float* __restrict__ Wv) {
  const int ng = blockIdx.x;
  const int mat = ng >> 10;
  const int h = (ng >> 6) & 15;
  const int n = ng & 63;
  const float* W = (mat == 0 ? Wq : (mat == 1 ? Wk : Wv));
  const float* src = W + (size_t)h * kD * kDK + n;
  __nv_bfloat16* dst = g_ws + (size_t)ng * kKS;
#pragma unroll
  for (int it = 0; it < 4; ++it) {
    int d = threadIdx.x + it * 256;
    unsigned short hh, ll;
    split1(src[(size_t)d * kDK], hh, ll);
    dst[d] = __ushort_as_bfloat16(hh);
    dst[1024 + d] = __ushort_as_bfloat16(hh);
    dst[2048 + d] = __ushort_as_bfloat16(ll);
  }
}

__global__ __launch_bounds__(256) void split_wo_kernel(
    const float* __restrict__ Wo) {
  const int n = blockIdx.x;
  __nv_bfloat16* dst = g_wos + (size_t)n * kKS;
#pragma unroll
  for (int it = 0; it < 4; ++it) {
    int d = threadIdx.x + it * 256;
    unsigned short hh, ll;
    split1(Wo[(size_t)d * kD + n], hh, ll);
    dst[d] = __ushort_as_bfloat16(hh);
    dst[1024 + d] = __ushort_as_bfloat16(hh);
    dst[2048 + d] = __ushort_as_bfloat16(ll);
  }
}

// ---------------------------------------------------------------------------
// HMMA GEMM (exact R8 configuration — measured 419 us, tensor 61%).
// C[128 x 128] = A[128 x 3072] * B[128 x 3072]^T (bf16 -> f32).
// 256 thr = 8 warps (2M x 4N), warp tile 64x32, cp.async double buffer.
// ---------------------------------------------------------------------------
__global__ __launch_bounds__(256) void mm_bf16_kernel(
    const __nv_bfloat16* __restrict__ A, const __nv_bfloat16* __restrict__ Bm,
    float* __restrict__ outP, int mode) {
  extern __shared__ char smem[];
  const unsigned sbase = smem_u32(smem);
  const unsigned aA[2] = {sbase, sbase + 16384};
  const unsigned aB[2] = {sbase + 32768, sbase + 49152};

  const int tid = threadIdx.x;
  const int wid = tid >> 5, lane = tid & 31;
  const int m0 = blockIdx.x * 128, n0 = blockIdx.y * 128;
  const int wm = (wid >> 2) * 64, wn = (wid & 3) * 32;
  const __nv_bfloat16* Asrc = A + (size_t)m0 * kKS;
  const __nv_bfloat16* Bsrc = Bm + (size_t)n0 * kKS;

  float acc[4][4][4];
#pragma unroll
  for (int mi = 0; mi < 4; ++mi)
#pragma unroll
    for (int ni = 0; ni < 4; ++ni)
#pragma unroll
      for (int r = 0; r < 4; ++r) acc[mi][ni][r] = 0.f;

#define STAGE(sbuf, ch)                                                        \
  do {                                                                         \
    _Pragma("unroll") for (int i_ = 0; i_ < 4; ++i_) {                         \
      int idx_ = tid + i_ * 256;                                               \
      int r_ = idx_ >> 3, sg_ = idx_ & 7;                                      \
      unsigned sw_ = ((unsigned)(sg_ ^ (r_ & 7))) << 4;                        \
      cpasync16(aA[sbuf] + r_ * 128 + sw_,                                     \
                Asrc + (size_t)r_ * kKS + (ch) * 64 + sg_ * 8);                \
      cpasync16(aB[sbuf] + r_ * 128 + sw_,                                     \
                Bsrc + (size_t)r_ * kKS + (ch) * 64 + sg_ * 8);                \
    }                                                                          \
    asm volatile("cp.async.commit_group;" ::: "memory");                       \
  } while (0)

  STAGE(0, 0);
  for (int ch = 0; ch < kKS / 64; ++ch) {
    const int s = ch & 1;
    if (ch < kKS / 64 - 1) {
      STAGE(s ^ 1, ch + 1);
      asm volatile("cp.async.wait_group 1;" ::: "memory");
    } else {
      asm volatile("cp.async.wait_group 0;" ::: "memory");
    }
    __syncthreads();
#pragma unroll
    for (int ks = 0; ks < 4; ++ks) {
      unsigned af[4][4], bf[4][2];
#pragma unroll
      for (int mi = 0; mi < 4; ++mi) {
        int row = wm + mi * 16 + (lane & 15);
        int cs = ks * 2 + (lane >> 4);
        ldmx4(af[mi], aA[s] + row * 128 + ((unsigned)(cs ^ (row & 7)) << 4));
      }
#pragma unroll
      for (int ni = 0; ni < 4; ++ni) {
        int row = wn + ni * 8 + (lane & 7);
        int cs = ks * 2 + ((lane >> 3) & 1);
        ldmx2(bf[ni], aB[s] + row * 128 + ((unsigned)(cs ^ (row & 7)) << 4));
      }
#pragma unroll
      for (int mi = 0; mi < 4; ++mi)
#pragma unroll
        for (int ni = 0; ni < 4; ++ni)
          mma_bf16(acc[mi][ni], af[mi], bf[ni][0], bf[ni][1]);
    }
    __syncthreads();
  }
#undef STAGE

  const int b = m0 >> 11;
  const int mat = n0 >> 10;
  float* qkvout = (mat == 0 ? g_q : (mat == 1 ? g_k : g_v));
#pragma unroll
  for (int mi = 0; mi < 4; ++mi) {
#pragma unroll
    for (int ni = 0; ni < 4; ++ni) {
      int rl = wm + mi * 16 + (lane >> 2);
      int n = n0 + wn + ni * 8 + (lane & 3) * 2;
      if (mode == 0) {
        int h = (n >> 6) & 15, dk = n & 63;
        size_t rowbase = (size_t)(b * kH + h) * kS + (m0 & (kS - 1));
        *(float2*)&qkvout[(rowbase + rl) * kDK + dk] =
            make_float2(acc[mi][ni][0], acc[mi][ni][1]);
        *(float2*)&qkvout[(rowbase + rl + 8) * kDK + dk] =
            make_float2(acc[mi][ni][2], acc[mi][ni][3]);
      } else {
        int m = m0 + rl;
        *(float2*)&outP[(size_t)m * kD + n] =
            make_float2(acc[mi][ni][0], acc[mi][ni][1]);
        *(float2*)&outP[(size_t)(m + 8) * kD + n] =
            make_float2(acc[mi][ni][2], acc[mi][ni][3]);
      }
    }
  }
}

// ---------------------------------------------------------------------------
// attn_smax: S ~= Qhi Khi^T via HMMA (single product), row max + shortlist.
// Dropped cross terms give score noise sigma ~2.3; margin 70 still includes
// everything above true_max - 36 (below fp32 visibility) with >2 sigma slack.
// smem: Qhi 16K + Khi 16K + cnt 512 + slots 8K = 41472 B.
// ---------------------------------------------------------------------------
__global__ __launch_bounds__(256) void attn_smax_kernel() {
  extern __shared__ char sm[];
  const unsigned sb = smem_u32(sm);
  const unsigned aQhi = sb, aKhi = sb + 16384;
  int* scnt = (int*)(sm + 32768);
  unsigned short* stid = (unsigned short*)(sm + 33280);

  const int tid = threadIdx.x;
  const int warp = tid >> 5, lane = tid & 31;
  const int qt = blockIdx.x, h = blockIdx.y, b = blockIdx.z;
  const int bh = b * kH + h;

  if (tid < 128) scnt[tid] = 0;

  const float* qsrc = g_q + ((size_t)bh * kS + qt * 128) * kDK;
#pragma unroll
  for (int it = 0; it < 4; ++it) {
    int idx = tid + it * 256;
    int row = idx >> 3, g = idx & 7;
    float v[8];
    float4 v0 = *(const float4*)&qsrc[(size_t)row * kDK + g * 8];
    float4 v1 = *(const float4*)&qsrc[(size_t)row * kDK + g * 8 + 4];
    v[0] = v0.x * 0.125f; v[1] = v0.y * 0.125f; v[2] = v0.z * 0.125f;
    v[3] = v0.w * 0.125f; v[4] = v1.x * 0.125f; v[5] = v1.y * 0.125f;
    v[6] = v1.z * 0.125f; v[7] = v1.w * 0.125f;
    unsigned sw = ((unsigned)(g ^ (row & 7))) << 4;
    *(uint4*)(sm + row * 128 + sw) = pack8hi(v);
  }

  float m0 = -3.0e38f, m1 = -3.0e38f;
  const int r0 = (warp << 4) + (lane >> 2);

  for (int kt = 0; kt < kS / 128; ++kt) {
    const float* ksrc = g_k + ((size_t)bh * kS + kt * 128) * kDK;
#pragma unroll
    for (int it = 0; it < 4; ++it) {
      int idx = tid + it * 256;
      int row = idx >> 3, g = idx & 7;
      float v[8];
      float4 v0 = *(const float4*)&ksrc[(size_t)row * kDK + g * 8];
      float4 v1 = *(const float4*)&ksrc[(size_t)row * kDK + g * 8 + 4];
      v[0] = v0.x; v[1] = v0.y; v[2] = v0.z; v[3] = v0.w;
      v[4] = v1.x; v[5] = v1.y; v[6] = v1.z; v[7] = v1.w;
      unsigned sw = ((unsigned)(g ^ (row & 7))) << 4;
      *(uint4*)(sm + 16384 + row * 128 + sw) = pack8hi(v);
    }
    __syncthreads();

    float acc[16][4];
#pragma unroll
    for (int tt = 0; tt < 16; ++tt)
#pragma unroll
      for (int j = 0; j < 4; ++j) acc[tt][j] = 0.f;

#pragma unroll
    for (int kc = 0; kc < 4; ++kc) {
      unsigned aHi[4];
      const int cs = kc * 2 + (lane >> 4);
      int rowq = (warp << 4) + (lane & 15);
      unsigned swq = ((unsigned)(cs ^ (rowq & 7))) << 4;
      ldmx4(aHi, aQhi + rowq * 128 + swq);
#pragma unroll
      for (int t3 = 0; t3 < 8; ++t3) {
        int rowb = t3 * 16 + (lane & 15);
        unsigned swb = ((unsigned)(cs ^ (rowb & 7))) << 4;
        unsigned kb[4];
        ldmx4(kb, aKhi + rowb * 128 + swb);
        mma_bf16(acc[t3 * 2], aHi, kb[0], kb[2]);
        mma_bf16(acc[t3 * 2 + 1], aHi, kb[1], kb[3]);
      }
    }

    float lm0 = -3.0e38f, lm1 = -3.0e38f;
#pragma unroll
    for (int tt = 0; tt < 16; ++tt) {
      lm0 = fmaxf(lm0, fmaxf(acc[tt][0], acc[tt][1]));
      lm1 = fmaxf(lm1, fmaxf(acc[tt][2], acc[tt][3]));
    }
    lm0 = fmaxf(lm0, __shfl_xor_sync(0xffffffffu, lm0, 1));
    lm0 = fmaxf(lm0, __shfl_xor_sync(0xffffffffu, lm0, 2));
    lm1 = fmaxf(lm1, __shfl_xor_sync(0xffffffffu, lm1, 1));
    lm1 = fmaxf(lm1, __shfl_xor_sync(0xffffffffu, lm1, 2));
    m0 = fmaxf(m0, lm0);
    m1 = fmaxf(m1, lm1);

    float th0 = m0 - 70.f, th1 = m1 - 70.f;
#pragma unroll
    for (int tt = 0; tt < 16; ++tt) {
      int tb = kt * 128 + tt * 8 + (lane & 3) * 2;
      if (acc[tt][0] > th0) {
        int i = atomicAdd(&scnt[r0], 1);
        if (i < kCap) stid[r0 * kCap + i] = (unsigned short)tb;
      }
      if (acc[tt][1] > th0) {
        int i = atomicAdd(&scnt[r0], 1);
        if (i < kCap) stid[r0 * kCap + i] = (unsigned short)(tb + 1);
      }
      if (acc[tt][2] > th1) {
        int i = atomicAdd(&scnt[r0 + 8], 1);
        if (i < kCap) stid[(r0 + 8) * kCap + i] = (unsigned short)tb;
      }
      if (acc[tt][3] > th1) {
        int i = atomicAdd(&scnt[r0 + 8], 1);
        if (i < kCap) stid[(r0 + 8) * kCap + i] = (unsigned short)(tb + 1);
      }
    }
    __syncthreads();
  }

  if (tid < 128) {
    size_t row_g = ((size_t)bh * 16 + qt) * 128 + tid;
    int c = scnt[tid];
    g_cnt[row_g] = c;
    int cc = c < kCap ? c : kCap;
    for (int i = 0; i < cc; ++i) g_slot[row_g * kCap + i] = stid[tid * kCap + i];
  }
}

// ---------------------------------------------------------------------------
// attn_gather: warp per q-row; exact fp32 softmax over shortlist; gather V.
// ---------------------------------------------------------------------------
__global__ __launch_bounds__(256) void attn_gather_kernel() {
  const int warp = threadIdx.x >> 5, lane = threadIdx.x & 31;
  const size_t row_g = (size_t)blockIdx.x * 8 + warp;
  const int qrow = (int)(row_g & 127);
  const int qt = (int)((row_g >> 7) & 15);
  const int h = (int)((row_g >> 11) & 15);
  const int b = (int)(row_g >> 15);
  const int bh = b * kH + h;
  const int sq = qt * 128 + qrow;

  const float* qp = g_q + ((size_t)bh * kS + sq) * kDK;
  const float* kb = g_k + (size_t)bh * kS * kDK;
  const float* vb = g_v + (size_t)bh * kS * kDK;
  float* outp = g_ao + ((size_t)b * kS + sq) * kD + h * kDK;

  const float q0 = qp[lane] * 0.125f, q1 = qp[lane + 32] * 0.125f;
  const int cnt = g_cnt[row_g];

  float m = -3.0e38f, l = 0.f, a0 = 0.f, a1 = 0.f;
  if (cnt <= kCap) {
    const unsigned short* sl = g_slot + row_g * kCap;
    for (int i = 0; i < cnt; ++i) {
      int t = sl[i];
      float d = q0 * kb[(size_t)t * kDK + lane] + q1 * kb[(size_t)t * kDK + lane + 32];
#pragma unroll
      for (int o = 16; o > 0; o >>= 1) d += __shfl_xor_sync(0xffffffffu, d, o);
      m = fmaxf(m, d);
    }
    for (int i = 0; i < cnt; ++i) {
      int t = sl[i];
      float d = q0 * kb[(size_t)t * kDK + lane] + q1 * kb[(size_t)t * kDK + lane + 32];
#pragma unroll
      for (int o = 16; o > 0; o >>= 1) d += __shfl_xor_sync(0xffffffffu, d, o);
      float p = __expf(d - m);
      l += p;
      a0 += p * vb[(size_t)t * kDK + lane];
      a1 += p * vb[(size_t)t * kDK + lane + 32];
    }
  } else {
    for (int t = 0; t < kS; ++t) {
      float d = q0 * kb[(size_t)t * kDK + lane] + q1 * kb[(size_t)t * kDK + lane + 32];
#pragma unroll
      for (int o = 16; o > 0; o >>= 1) d += __shfl_xor_sync(0xffffffffu, d, o);
      float v0 = vb[(size_t)t * kDK + lane], v1 = vb[(size_t)t * kDK + lane + 32];
      if (d > m) {
        float c = __expf(m - d);
        m = d;
        l = l * c + 1.f;
        a0 = a0 * c + v0;
        a1 = a1 * c + v1;
      } else {
        float p = __expf(d - m);
        l += p;
        a0 += p * v0;
        a1 += p * v1;
      }
    }
  }
  float inv = 1.f / l;
  outp[lane] = a0 * inv;
  outp[lane + 32] = a1 * inv;
}

// ---------------------------------------------------------------------------
extern "C" void kernel_launch(void* const* d_in, const int* in_sizes, int n_in,
                              void* d_out, int out_size) {
  (void)in_sizes; (void)n_in; (void)out_size;
  const float* x  = (const float*)d_in[0];
  const float* Wq = (const float*)d_in[1];
  const float* Wk = (const float*)d_in[2];
  const float* Wv = (const float*)d_in[3];
  const float* Wo = (const float*)d_in[4];
  float* out = (float*)d_out;

  static int attr_set = 0;
  if (!attr_set) {
    cudaFuncSetAttribute(mm_bf16_kernel,
                         cudaFuncAttributeMaxDynamicSharedMemorySize, 65536);
    cudaFuncSetAttribute(attn_smax_kernel,
                         cudaFuncAttributeMaxDynamicSharedMemorySize, 41472);
    attr_set = 1;
  }

  __nv_bfloat16* xs;  cudaGetSymbolAddress((void**)&xs, g_xs);
  __nv_bfloat16* ws;  cudaGetSymbolAddress((void**)&ws, g_ws);
  __nv_bfloat16* wos; cudaGetSymbolAddress((void**)&wos, g_wos);
  __nv_bfloat16* aos; cudaGetSymbolAddress((void**)&aos, g_aos);
  float* aop;         cudaGetSymbolAddress((void**)&aop, g_ao);

  split_act_kernel<<<kB * kS, 256>>>(x, xs);
  split_w_kernel<<<3 * kH * kDK, 256>>>(Wq, Wk, Wv);
  split_wo_kernel<<<kD, 256>>>(Wo);
  mm_bf16_kernel<<<dim3(kB * kS / 128, kKS / 128), 256, 65536>>>(xs, ws, nullptr, 0);
  attn_smax_kernel<<<dim3(kS / 128, kH, kB), 256, 41472>>>();
  attn_gather_kernel<<<kB * kH * kS / 8, 256>>>();
  split_act_kernel<<<kB * kS, 256>>>(aop, aos);
  mm_bf16_kernel<<<dim3(kB * kS / 128, kD / 128), 256, 65536>>>(aos, wos, out, 1);
}